// round 8
// baseline (speedup 1.0000x reference)
#include <cuda_runtime.h>
#include <stdint.h>

#define NSEG   16384
#define SEGLEN 1024
#define KSEL   128
#define NTHR   256
#define WPB    8
#define NBLK   (NSEG / WPB)

// f = x*1280 - 1075.2 maps x in [0.84, 0.915) -> f in [0,96); bin 96 = hi (x>=0.915)
#define INV_W  1280.0f
#define F_C    (-1075.2f)
#define NBAND  96
#define HIBIN  96
#define SLOTS  16      // per-lane gather slots; in-range count/lane ~ Bin(32, 0.15)
#define BBUFN  8
#define NSLOT  256

__device__ float    g_part[NSLOT];   // zero-init at load
__device__ unsigned g_done = 0;

#define FULLM 0xffffffffu

__device__ __forceinline__ float warpSumF(float v) {
    #pragma unroll
    for (int o = 16; o; o >>= 1) v += __shfl_xor_sync(FULLM, v, o);
    return v;
}

__global__ __launch_bounds__(NTHR, 6)
void mil_kernel(const float* __restrict__ y_pred, const float* __restrict__ y,
                float* __restrict__ out) {
    __shared__ int   s_hist[WPB][HIBIN + 1];
    __shared__ float s_gath[WPB][SLOTS * 32];
    __shared__ float s_bbuf[WPB][BBUFN];
    __shared__ int   s_bcnt[WPB];
    __shared__ float s_red[WPB];
    __shared__ int   s_islast;

    const int tid  = threadIdx.x;
    const int lane = tid & 31;
    const int w    = tid >> 5;
    const int seg  = blockIdx.x * WPB + w;

    int*   hist = &s_hist[w][0];
    float* gath = &s_gath[w][0];

    // warp-local init (no block barrier in hot path)
    hist[lane] = 0; hist[lane + 32] = 0; hist[lane + 64] = 0;
    if (lane == 0) { hist[HIBIN] = 0; s_bcnt[w] = 0; }
    __syncwarp();

    const float4* base = reinterpret_cast<const float4*>(y_pred + (size_t)seg * SEGLEN);
    const float t = __ldg(y + (size_t)seg * SEGLEN);   // label: segment-constant

    // ---- pass 1: stream 32 elems/lane; only ~15% take the slow path ----
    int cnt = 0;
    #pragma unroll
    for (int c = 0; c < 8; c++) {
        float4 q = base[lane + c * 32];
        float xs[4] = {q.x, q.y, q.z, q.w};
        #pragma unroll
        for (int j = 0; j < 4; j++) {
            float x = xs[j];
            float f = fmaf(x, INV_W, F_C);
            if (f >= 0.0f) {
                int b = min((int)f, HIBIN);
                atomicAdd(&hist[b], 1);
                if (cnt < SLOTS) gath[lane + cnt * 32] = x;
                cnt++;
            }
        }
    }
    __syncwarp();                                     // hist visible

    const int c_hi = hist[HIBIN];                     // LDS broadcast
    const int need = KSEL - c_hi;

    // ---- suffix scan of 96 band bins; locate boundary bin b* ----
    const int c0 = hist[3 * lane], c1 = hist[3 * lane + 1], c2 = hist[3 * lane + 2];
    const int own = c0 + c1 + c2;
    int inc = own;
    #pragma unroll
    for (int o = 1; o < 32; o <<= 1) {
        int v = __shfl_down_sync(FULLM, inc, o);
        if (lane + o < 32) inc += v;
    }
    const int exc   = inc - own;
    const int total = __shfl_sync(FULLM, inc, 0);

    bool of = (cnt > SLOTS);
    bool fb = __ballot_sync(FULLM, of) != 0u || (need <= 0) || (total < need);

    int bstar = 0, above = 0;
    {
        bool here = !fb && (exc < need) && (need <= inc);
        int lb = 0, la = 0;
        if (here) {
            if      (exc + c2 >= need)      { lb = 3 * lane + 2; la = exc; }
            else if (exc + c2 + c1 >= need) { lb = 3 * lane + 1; la = exc + c2; }
            else                            { lb = 3 * lane;     la = exc + c2 + c1; }
        }
        unsigned bal = __ballot_sync(FULLM, here);
        if (bal == 0) fb = true;
        else {
            int src = __ffs(bal) - 1;
            bstar = __shfl_sync(FULLM, lb, src);
            above = __shfl_sync(FULLM, la, src);
        }
    }

    float loss = 0.f;    // valid on lane 0

    if (!fb) {
        // ---- pass 2: rescan gathered slots (~5/lane): sum bins > b*, gather == b*
        float sa = 0.f;
        for (int k = 0; k < cnt; k++) {
            float x = gath[lane + k * 32];
            int b = min((int)fmaf(x, INV_W, F_C), HIBIN);   // same formula
            if (b > bstar) sa += x;                          // includes hi bin
            else if (b == bstar) {
                int i2 = atomicAdd(&s_bcnt[w], 1);
                if (i2 < BBUFN) s_bbuf[w][i2] = x;
            }
        }
        __syncwarp();
        const int mm = s_bcnt[w];
        if (mm > BBUFN) fb = true;
        else {
            const int r = need - above;                      // 1..mm
            if (lane < mm) {
                unsigned mv = __float_as_uint(s_bbuf[w][lane]);  // positive: int order
                int rk = 0;
                for (int j = 0; j < mm; j++) {
                    unsigned xv = __float_as_uint(s_bbuf[w][j]);
                    rk += (xv > mv) || (xv == mv && j < lane);
                }
                if (rk < r) sa += __uint_as_float(mv);
            }
            sa = warpSumF(sa);
            if (lane == 0) {
                float p = sa * (1.0f / KSEL);
                loss = t * logf(p) + (1.0f - t) * log1pf(-p);
            }
        }
    }

    if (fb) {
        // ---- exact fallback: radix select, reload from L2 (rare) ----
        unsigned prefix = 0;
        for (int bit = 30; bit >= 0; bit--) {
            unsigned test = prefix | (1u << bit);
            int cc = 0;
            #pragma unroll
            for (int c = 0; c < 8; c++) {
                float4 q = base[lane + c * 32];
                cc += (__float_as_uint(q.x) >= test) + (__float_as_uint(q.y) >= test)
                    + (__float_as_uint(q.z) >= test) + (__float_as_uint(q.w) >= test);
            }
            cc = __reduce_add_sync(FULLM, cc);
            if (cc >= KSEL) prefix = test;
        }
        float S = 0.f; int G = 0;
        #pragma unroll
        for (int c = 0; c < 8; c++) {
            float4 q = base[lane + c * 32];
            if (__float_as_uint(q.x) > prefix) { G++; S += q.x; }
            if (__float_as_uint(q.y) > prefix) { G++; S += q.y; }
            if (__float_as_uint(q.z) > prefix) { G++; S += q.z; }
            if (__float_as_uint(q.w) > prefix) { G++; S += q.w; }
        }
        S = warpSumF(S);
        G = __reduce_add_sync(FULLM, G);
        if (lane == 0) {
            float kthv = __uint_as_float(prefix);
            float p = (S + (float)(KSEL - G) * kthv) * (1.0f / KSEL);
            loss = t * logf(p) + (1.0f - t) * log1pf(-p);
        }
    }

    if (lane == 0) atomicAdd(&g_part[seg & (NSLOT - 1)], loss);

    // ---- fused finalize: last block reduces the 256 partials ----
    __syncthreads();
    if (tid == 0) {
        __threadfence();
        unsigned old = atomicAdd(&g_done, 1u);
        s_islast = (old == NBLK - 1) ? 1 : 0;
    }
    __syncthreads();
    if (s_islast) {
        __threadfence();
        float v = g_part[tid];
        g_part[tid] = 0.0f;                   // reset for next graph replay
        v = warpSumF(v);
        if (lane == 0) s_red[w] = v;
        __syncthreads();
        if (tid == 0) {
            float acc = 0.f;
            #pragma unroll
            for (int i = 0; i < WPB; i++) acc += s_red[i];
            out[0] = -acc * (1.0f / NSEG);
            g_done = 0;                       // reset for next graph replay
        }
    }
}

extern "C" void kernel_launch(void* const* d_in, const int* in_sizes, int n_in,
                              void* d_out, int out_size) {
    const float* y_pred = (const float*)d_in[0];
    const float* yv     = (const float*)d_in[1];
    (void)in_sizes; (void)n_in; (void)out_size;

    mil_kernel<<<NBLK, NTHR>>>(y_pred, yv, (float*)d_out);
}